// round 1
// baseline (speedup 1.0000x reference)
#include <cuda_runtime.h>
#include <math.h>

// Problem constants
#define BB 2
#define TT 2048
#define CC 1024
#define NH 16
#define HD 64
#define MROWS (BB*TT)      // 4096
#define QKVN  (3*CC)       // 3072

// Scratch (allocation-free rule: __device__ globals)
__device__ float g_qkv[MROWS * QKVN];   // [4096, 3072]
__device__ float g_y[MROWS * CC];       // [4096, 1024]

// ---------------------------------------------------------------------------
// Tiled FP32 GEMM with bias: out[M,N] = A[M,K] @ W[K,N] + bias[N]
// BM=BN=128, BK=16, 256 threads, 8x8 per-thread tile.
// Requires M%128==0, N%128==0, K%16==0 (true for all our shapes).
// ---------------------------------------------------------------------------
__global__ void __launch_bounds__(256) sgemm_bias_kernel(
    const float* __restrict__ A, const float* __restrict__ W,
    const float* __restrict__ bias, float* __restrict__ out,
    int M, int N, int K)
{
    constexpr int BM = 128, BN = 128, BK = 16;
    __shared__ float As[BK][BM + 4];
    __shared__ float Bs[BK][BN + 4];

    const int tid = threadIdx.x;
    const int tx = tid & 15;    // n direction
    const int ty = tid >> 4;    // m direction
    const int m0 = blockIdx.y * BM;
    const int n0 = blockIdx.x * BN;

    float acc[8][8];
#pragma unroll
    for (int i = 0; i < 8; i++)
#pragma unroll
        for (int j = 0; j < 8; j++) acc[i][j] = 0.0f;

    // A-load mapping: 512 float4 per tile (128 rows x 4 f4/row)
    const int ar0 = tid >> 2;   // row 0..63 (second pass +64)
    const int ac0 = tid & 3;    // f4 column within the 16-wide K slab

    for (int k0 = 0; k0 < K; k0 += BK) {
        // Load A tile (transposed into As[k][m])
#pragma unroll
        for (int i = 0; i < 2; i++) {
            int row = ar0 + i * 64;
            float4 v = *(const float4*)&A[(size_t)(m0 + row) * K + k0 + ac0 * 4];
            As[ac0 * 4 + 0][row] = v.x;
            As[ac0 * 4 + 1][row] = v.y;
            As[ac0 * 4 + 2][row] = v.z;
            As[ac0 * 4 + 3][row] = v.w;
        }
        // Load B tile (natural layout Bs[k][n])
#pragma unroll
        for (int i = 0; i < 2; i++) {
            int p = tid + i * 256;
            int row = p >> 5, c4 = p & 31;
            *(float4*)&Bs[row][c4 * 4] =
                *(const float4*)&W[(size_t)(k0 + row) * N + n0 + c4 * 4];
        }
        __syncthreads();

#pragma unroll
        for (int k = 0; k < BK; k++) {
            float a[8], b[8];
#pragma unroll
            for (int i = 0; i < 8; i++) a[i] = As[k][ty * 8 + i];
#pragma unroll
            for (int j = 0; j < 8; j++) b[j] = Bs[k][tx * 8 + j];
#pragma unroll
            for (int i = 0; i < 8; i++)
#pragma unroll
                for (int j = 0; j < 8; j++)
                    acc[i][j] += a[i] * b[j];
        }
        __syncthreads();
    }

    // Epilogue: add bias, vectorized store
#pragma unroll
    for (int i = 0; i < 8; i++) {
        int r = m0 + ty * 8 + i;
#pragma unroll
        for (int j = 0; j < 8; j += 4) {
            int cn = n0 + tx * 8 + j;
            float4 v;
            v.x = acc[i][j + 0] + bias[cn + 0];
            v.y = acc[i][j + 1] + bias[cn + 1];
            v.z = acc[i][j + 2] + bias[cn + 2];
            v.w = acc[i][j + 3] + bias[cn + 3];
            *(float4*)&out[(size_t)r * N + cn] = v;
        }
    }
}

// ---------------------------------------------------------------------------
// Causal flash attention, fp32.
// Grid: (T/128, B*NH). Block: 128 threads, one query per thread.
// Q (64 floats) and O-accumulator (64 floats) live in registers; K/V tiles of
// 64 keys live in SMEM (broadcast reads -> conflict-free). Online softmax in
// chunks of 8 keys to bound register pressure.
// Reads Q/K/V straight out of the packed qkv buffer [4096, 3072].
// Writes y in [b, t, h, d] layout ([4096, 1024]).
// ---------------------------------------------------------------------------
__global__ void __launch_bounds__(128) flash_attn_kernel(
    const float* __restrict__ qkv, float* __restrict__ y)
{
    const int qblk = blockIdx.x;          // 0..15
    const int bh   = blockIdx.y;          // 0..31
    const int b    = bh >> 4;
    const int h    = bh & 15;
    const int tid  = threadIdx.x;
    const int q    = qblk * 128 + tid;    // global query index within sequence
    const float scale = 0.125f;           // 1/sqrt(64)

    __shared__ float4 ks[64][16];
    __shared__ float4 vs[64][16];

    // Load query row into registers
    float4 qv[16];
    const float* qrow = qkv + (size_t)(b * TT + q) * QKVN + h * HD;
#pragma unroll
    for (int i = 0; i < 16; i++) qv[i] = *(const float4*)(qrow + i * 4);

    float4 acc[16];
#pragma unroll
    for (int i = 0; i < 16; i++) acc[i] = make_float4(0.f, 0.f, 0.f, 0.f);
    float m = -INFINITY, l = 0.0f;

    const int kend = qblk * 128 + 128;   // exclusive upper bound on keys needed
    for (int kt = 0; kt < kend; kt += 64) {
        // Cooperative load of 64 keys + 64 values (each thread: 8 float4 per tensor)
        for (int p = tid; p < 1024; p += 128) {
            int r = p >> 4, c = p & 15;
            const float* krow = qkv + (size_t)(b * TT + kt + r) * QKVN + CC + h * HD;
            ks[r][c] = *(const float4*)(krow + c * 4);
            vs[r][c] = *(const float4*)(krow + CC + c * 4);
        }
        __syncthreads();

#pragma unroll 1
        for (int c0 = 0; c0 < 64; c0 += 8) {
            float s[8];
            float cmax = -INFINITY;
#pragma unroll
            for (int jj = 0; jj < 8; jj++) {
                int j = c0 + jj;
                float dot = 0.0f;
#pragma unroll
                for (int i = 0; i < 16; i++) {
                    float4 kv = ks[j][i];
                    dot += qv[i].x * kv.x + qv[i].y * kv.y +
                           qv[i].z * kv.z + qv[i].w * kv.w;
                }
                s[jj] = (kt + j <= q) ? dot * scale : -INFINITY;
                cmax = fmaxf(cmax, s[jj]);
            }
            if (cmax > -INFINITY) {
                float m_new = fmaxf(m, cmax);
                float corr  = __expf(m - m_new);   // m==-inf -> 0
                l *= corr;
#pragma unroll
                for (int i = 0; i < 16; i++) {
                    acc[i].x *= corr; acc[i].y *= corr;
                    acc[i].z *= corr; acc[i].w *= corr;
                }
#pragma unroll
                for (int jj = 0; jj < 8; jj++) {
                    float p = __expf(s[jj] - m_new);
                    l += p;
                    int j = c0 + jj;
#pragma unroll
                    for (int i = 0; i < 16; i++) {
                        float4 vv = vs[j][i];
                        acc[i].x += p * vv.x; acc[i].y += p * vv.y;
                        acc[i].z += p * vv.z; acc[i].w += p * vv.w;
                    }
                }
                m = m_new;
            }
        }
        __syncthreads();
    }

    const float inv = 1.0f / l;
    float* yrow = y + (size_t)(b * TT + q) * CC + h * HD;
#pragma unroll
    for (int i = 0; i < 16; i++) {
        float4 v;
        v.x = acc[i].x * inv; v.y = acc[i].y * inv;
        v.z = acc[i].z * inv; v.w = acc[i].w * inv;
        *(float4*)(yrow + i * 4) = v;
    }
}

// ---------------------------------------------------------------------------
// Launch
// ---------------------------------------------------------------------------
extern "C" void kernel_launch(void* const* d_in, const int* in_sizes, int n_in,
                              void* d_out, int out_size)
{
    const float* x     = (const float*)d_in[0];   // [2,2048,1024]
    const float* w_qkv = (const float*)d_in[1];   // [1024,3072]
    const float* b_qkv = (const float*)d_in[2];   // [3072]
    const float* w_out = (const float*)d_in[3];   // [1024,1024]
    const float* b_out = (const float*)d_in[4];   // [1024]
    float* out = (float*)d_out;                   // [2,2048,1024]

    float *qkv, *y;
    cudaGetSymbolAddress((void**)&qkv, g_qkv);
    cudaGetSymbolAddress((void**)&y, g_y);

    // 1) QKV projection: [4096,1024] @ [1024,3072] + b_qkv
    sgemm_bias_kernel<<<dim3(QKVN / 128, MROWS / 128), 256>>>(
        x, w_qkv, b_qkv, qkv, MROWS, QKVN, CC);

    // 2) Causal multi-head attention -> y [4096,1024] in (b,t,h,d) layout
    flash_attn_kernel<<<dim3(TT / 128, BB * NH), 128>>>(qkv, y);

    // 3) Output projection: [4096,1024] @ [1024,1024] + b_out
    sgemm_bias_kernel<<<dim3(CC / 128, MROWS / 128), 256>>>(
        y, w_out, b_out, out, MROWS, CC, CC);
}